// round 1
// baseline (speedup 1.0000x reference)
#include <cuda_runtime.h>

#define B_   64
#define T_   512
#define D_   256
#define U_   512
#define G3   1536
#define NBLK 128
#define NTHR 256

// ---------------- device scratch (no allocations allowed) ----------------
__device__ float g_gx[(size_t)2 * T_ * B_ * G3];   // [dir][t][b][3U] gate preacts (~400MB)
__device__ float g_h [2 * B_ * U_];                // hidden state per dir
__device__ float g_u [2 * B_ * U_];                // update gate per step
__device__ float g_rh[2 * B_ * U_];                // r * h per step
__device__ unsigned int          g_bar_count = 0;
__device__ volatile unsigned int g_bar_gen   = 0;

// Software grid barrier. Safe across graph replays: gen is monotone,
// count returns to 0 after every barrier.
__device__ __forceinline__ void grid_barrier() {
    __threadfence();
    __syncthreads();
    if (threadIdx.x == 0) {
        unsigned g = g_bar_gen;
        unsigned prev = atomicAdd(&g_bar_count, 1u);
        if (prev == NBLK - 1) {
            g_bar_count = 0;
            __threadfence();
            g_bar_gen = g + 1;
        } else {
            while (g_bar_gen == g) { __nanosleep(64); }
        }
    }
    __syncthreads();
    __threadfence();
}

__device__ __forceinline__ float sigmoidf_(float z) {
    return 1.0f / (1.0f + __expf(-z));
}

// =====================================================================
// Kernel A: input projections for BOTH directions in one GEMM.
//   C[32768, 3072] = x[32768,256] @ [Wx_f | Wx_b], scattered into g_gx
//   with time reversal for the backward direction.
// Tile 64x64x16, 256 threads, 4x4 micro-tile.
// =====================================================================
__global__ void __launch_bounds__(256) k_inproj(
    const float* __restrict__ x,
    const float* __restrict__ Wxf,
    const float* __restrict__ Wxb)
{
    __shared__ __align__(16) float As[16 * 64];   // [k][m] transposed
    __shared__ __align__(16) float Bs[16 * 64];   // [k][n]

    const int tid = threadIdx.x;
    const int m0  = blockIdx.x * 64;           // row tile over B*T
    const int n0g = blockIdx.y * 64;           // 0..3071
    const int dir = (n0g >= G3) ? 1 : 0;
    const float* __restrict__ W = dir ? Wxb : Wxf;
    const int n0 = n0g - dir * G3;

    const int bg = tid >> 4;      // 0..15 -> 4 rows each
    const int ng = tid & 15;      // 0..15 -> 4 cols each
    const int ar = tid >> 2, aq = tid & 3;   // A-tile load mapping
    const int bk = tid >> 4, bc = tid & 15;  // B-tile load mapping

    float acc[4][4];
#pragma unroll
    for (int i = 0; i < 4; i++)
#pragma unroll
        for (int j = 0; j < 4; j++) acc[i][j] = 0.0f;

    for (int k0 = 0; k0 < D_; k0 += 16) {
        float4 av = *reinterpret_cast<const float4*>(x + (size_t)(m0 + ar) * D_ + k0 + aq * 4);
        float4 bv = *reinterpret_cast<const float4*>(W + (size_t)(k0 + bk) * G3 + n0 + bc * 4);
        __syncthreads();
        As[(aq * 4 + 0) * 64 + ar] = av.x;
        As[(aq * 4 + 1) * 64 + ar] = av.y;
        As[(aq * 4 + 2) * 64 + ar] = av.z;
        As[(aq * 4 + 3) * 64 + ar] = av.w;
        *reinterpret_cast<float4*>(&Bs[bk * 64 + bc * 4]) = bv;
        __syncthreads();
#pragma unroll
        for (int kk = 0; kk < 16; kk++) {
            float4 a4 = *reinterpret_cast<const float4*>(&As[kk * 64 + bg * 4]);
            float4 b4 = *reinterpret_cast<const float4*>(&Bs[kk * 64 + ng * 4]);
            float a[4] = {a4.x, a4.y, a4.z, a4.w};
            float b[4] = {b4.x, b4.y, b4.z, b4.w};
#pragma unroll
            for (int i = 0; i < 4; i++)
#pragma unroll
                for (int j = 0; j < 4; j++) acc[i][j] += a[i] * b[j];
        }
    }

    // scatter: row m -> (b, s); backward dir stores at t = T-1-s
#pragma unroll
    for (int i = 0; i < 4; i++) {
        int m = m0 + bg * 4 + i;
        int b = m >> 9;
        int s = m & 511;
        int t = dir ? (T_ - 1 - s) : s;
        float* dst = g_gx + (((size_t)dir * T_ + t) * B_ + b) * G3 + n0 + ng * 4;
        *reinterpret_cast<float4*>(dst) =
            make_float4(acc[i][0], acc[i][1], acc[i][2], acc[i][3]);
    }
}

// =====================================================================
// Kernel B: persistent bidirectional GRU scan.
// 128 blocks: blocks [0,64) = forward dir, [64,128) = backward dir.
// Per step:
//   Phase A: z = h @ Wh[:, :1024]; u = sig(gx_u+z+b), r = sig(gx_r+z+b);
//            store u, r*h.           (16 cols/block, K-split 4, 4x4 micro)
//   Phase B: c = (r*h) @ Wh[:,1024:]; hh = tanh(gx_c+c+b);
//            h' = h + u*(hh-h); store h', write output.
//            (8 cols/block, K-split 8, 4x4 micro)
// Wh is read through L1 (persists across the whole launch); h/u/rh use
// __ldcg/__stcg for cross-SM L2 coherence.
// =====================================================================
__global__ void __launch_bounds__(256, 1) k_scan(
    const float* __restrict__ Whf, const float* __restrict__ Whb,
    const float* __restrict__ bf,  const float* __restrict__ bb,
    float* __restrict__ out)
{
    __shared__ __align__(16) float s_stage[4096];  // operand staging (transposed)
    __shared__ float s_red[4096];                  // K-split partials

    const int tid = threadIdx.x;
    const int blk = blockIdx.x;
    const int dir = blk >> 6;
    const int sub = blk & 63;

    const float* __restrict__ Wh   = dir ? Whb : Whf;
    const float* __restrict__ bias = dir ? bb : bf;
    float* hbuf  = g_h  + dir * (B_ * U_);
    float* ubuf  = g_u  + dir * (B_ * U_);
    float* rhbuf = g_rh + dir * (B_ * U_);
    const float* gxbase = g_gx + (size_t)dir * T_ * B_ * G3;

    const int cbaseA = sub * 16;   // cols within [0,1024)  (u then r)
    const int cbaseB = sub * 8;    // cols within [0,512)   (candidate)

    // zero both dirs' h (2*64*512 = 65536 floats, 2 per thread)
    {
        int idx = (blk * NTHR + tid) * 2;
        __stcg(&g_h[idx], 0.0f);
        __stcg(&g_h[idx + 1], 0.0f);
    }
    grid_barrier();

    // Phase A thread mapping: kg=K-split group (128 k each), 4x4 micro over 64b x 16c
    const int kgA = tid >> 6;
    const int t2  = tid & 63;
    const int b0A = (t2 >> 2) << 2;
    const int c0A = (t2 & 3) << 2;
    // Phase B mapping: kg (64 k each), 4x4 micro over 64b x 8c
    const int kgB = tid >> 5;
    const int t3  = tid & 31;
    const int b0B = (t3 >> 1) << 2;
    const int c0B = (t3 & 1) << 2;

    for (int t = 0; t < T_; t++) {
        const float* gxt = gxbase + (size_t)t * B_ * G3;

        // ================= Phase A =================
        {
            float acc[4][4];
#pragma unroll
            for (int i = 0; i < 4; i++)
#pragma unroll
                for (int j = 0; j < 4; j++) acc[i][j] = 0.0f;

            const int kb = kgA << 7;
            for (int ch = 0; ch < 8; ch++) {
                const int k0 = kb + (ch << 4);
                // stage h[64][k0:k0+16] transposed -> s_stage[kg][kk][b]
#pragma unroll
                for (int j = 0; j < 4; j++) {
                    int f  = (j << 6) + t2;          // float4 id 0..255
                    int bl = f >> 2, q = f & 3;
                    float4 v = __ldcg(reinterpret_cast<const float4*>(
                        hbuf + bl * U_ + k0 + (q << 2)));
                    int base = ((kgA << 4) + (q << 2)) * 64 + bl;
                    s_stage[base]       = v.x;
                    s_stage[base + 64]  = v.y;
                    s_stage[base + 128] = v.z;
                    s_stage[base + 192] = v.w;
                }
                __syncthreads();
#pragma unroll
                for (int kk = 0; kk < 16; kk++) {
                    float4 h4 = *reinterpret_cast<const float4*>(
                        &s_stage[((kgA << 4) + kk) * 64 + b0A]);
                    float4 w4 = *reinterpret_cast<const float4*>(
                        Wh + (size_t)(k0 + kk) * G3 + cbaseA + c0A);
                    float a[4] = {h4.x, h4.y, h4.z, h4.w};
                    float w[4] = {w4.x, w4.y, w4.z, w4.w};
#pragma unroll
                    for (int i = 0; i < 4; i++)
#pragma unroll
                        for (int j = 0; j < 4; j++) acc[i][j] += a[i] * w[j];
                }
                __syncthreads();
            }
#pragma unroll
            for (int i = 0; i < 4; i++)
#pragma unroll
                for (int j = 0; j < 4; j++)
                    s_red[(kgA << 10) + (b0A + i) * 16 + c0A + j] = acc[i][j];
            __syncthreads();
#pragma unroll
            for (int m = 0; m < 4; m++) {
                int oid = (tid << 2) + m;       // 0..1023 == b*16 + c
                int b = oid >> 4, c = oid & 15;
                float z = s_red[oid] + s_red[1024 + oid] +
                          s_red[2048 + oid] + s_red[3072 + oid];
                int cg = cbaseA + c;
                float pre = z + __ldg(gxt + (size_t)b * G3 + cg) + __ldg(bias + cg);
                float sg = sigmoidf_(pre);
                if (cg < U_) {
                    __stcg(ubuf + b * U_ + cg, sg);
                } else {
                    int cc = cg - U_;
                    float hold = __ldcg(hbuf + b * U_ + cc);
                    __stcg(rhbuf + b * U_ + cc, sg * hold);
                }
            }
        }
        grid_barrier();

        // ================= Phase B =================
        {
            float acc[4][4];
#pragma unroll
            for (int i = 0; i < 4; i++)
#pragma unroll
                for (int j = 0; j < 4; j++) acc[i][j] = 0.0f;

            const int kb = kgB << 6;
            for (int ch = 0; ch < 8; ch++) {
                const int k0 = kb + (ch << 3);
#pragma unroll
                for (int j = 0; j < 4; j++) {
                    int f  = (j << 5) + t3;          // float4 id 0..127
                    int bl = f >> 1, q = f & 1;
                    float4 v = __ldcg(reinterpret_cast<const float4*>(
                        rhbuf + bl * U_ + k0 + (q << 2)));
                    int base = ((kgB << 3) + (q << 2)) * 64 + bl;
                    s_stage[base]       = v.x;
                    s_stage[base + 64]  = v.y;
                    s_stage[base + 128] = v.z;
                    s_stage[base + 192] = v.w;
                }
                __syncthreads();
#pragma unroll
                for (int kk = 0; kk < 8; kk++) {
                    float4 h4 = *reinterpret_cast<const float4*>(
                        &s_stage[((kgB << 3) + kk) * 64 + b0B]);
                    float4 w4 = *reinterpret_cast<const float4*>(
                        Wh + (size_t)(k0 + kk) * G3 + 1024 + cbaseB + c0B);
                    float a[4] = {h4.x, h4.y, h4.z, h4.w};
                    float w[4] = {w4.x, w4.y, w4.z, w4.w};
#pragma unroll
                    for (int i = 0; i < 4; i++)
#pragma unroll
                        for (int j = 0; j < 4; j++) acc[i][j] += a[i] * w[j];
                }
                __syncthreads();
            }
#pragma unroll
            for (int i = 0; i < 4; i++)
#pragma unroll
                for (int j = 0; j < 4; j++)
                    s_red[(kgB << 9) + (b0B + i) * 8 + c0B + j] = acc[i][j];
            __syncthreads();
#pragma unroll
            for (int m = 0; m < 2; m++) {
                int oid = (tid << 1) + m;       // 0..511 == b*8 + c
                int b = oid >> 3, c = oid & 7;
                float z = 0.0f;
#pragma unroll
                for (int kg = 0; kg < 8; kg++) z += s_red[(kg << 9) + oid];
                int cg = cbaseB + c;
                float pre = z + __ldg(gxt + (size_t)b * G3 + 1024 + cg) +
                            __ldg(bias + 1024 + cg);
                float hh   = tanhf(pre);
                float uu   = __ldcg(ubuf + b * U_ + cg);
                float hold = __ldcg(hbuf + b * U_ + cg);
                float hnew = hold + uu * (hh - hold);
                __stcg(hbuf + b * U_ + cg, hnew);
                out[((size_t)b * T_ + t) * 1024 + dir * U_ + cg] = hnew;
            }
        }
        grid_barrier();
    }
}

// =====================================================================
extern "C" void kernel_launch(void* const* d_in, const int* in_sizes, int n_in,
                              void* d_out, int out_size)
{
    const float* x   = (const float*)d_in[0];
    const float* Wxf = (const float*)d_in[1];
    const float* Whf = (const float*)d_in[2];
    const float* bf  = (const float*)d_in[3];
    const float* Wxb = (const float*)d_in[4];
    const float* Whb = (const float*)d_in[5];
    const float* bb  = (const float*)d_in[6];
    float* out = (float*)d_out;

    dim3 gA(512, 48);                 // (32768/64 rows, 3072/64 cols)
    k_inproj<<<gA, 256>>>(x, Wxf, Wxb);
    k_scan<<<NBLK, NTHR>>>(Whf, Whb, bf, bb, out);
}

// round 2
// speedup vs baseline: 1.3492x; 1.3492x over previous
#include <cuda_runtime.h>

#define B_   64
#define T_   512
#define D_   256
#define U_   512
#define G3   1536
#define NBLK 128
#define NTHR 512

// ---------------- device scratch (no allocations allowed) ----------------
__device__ float g_gx[(size_t)2 * T_ * B_ * G3];   // [dir][t][b][3U] gate preacts
__device__ float g_h [2 * B_ * U_];                // hidden state per dir
__device__ float g_u [2 * B_ * U_];                // update gate per step
__device__ float g_rh[2 * B_ * U_];                // r * h per step
__device__ unsigned int          g_barc[2] = {0, 0};
__device__ volatile unsigned int g_barg[2] = {0, 0};

// Per-direction software barrier over 64 blocks. Replay-safe: gen is
// monotone, count returns to 0 after each barrier.
__device__ __forceinline__ void dir_barrier(int dir) {
    __threadfence();
    __syncthreads();
    if (threadIdx.x == 0) {
        unsigned g = g_barg[dir];
        unsigned prev = atomicAdd(&g_barc[dir], 1u);
        if (prev == 63u) {
            g_barc[dir] = 0u;
            __threadfence();
            g_barg[dir] = g + 1u;
        } else {
            while (g_barg[dir] == g) { __nanosleep(32); }
        }
    }
    __syncthreads();
}

__device__ __forceinline__ float sigmoidf_(float z) {
    return 1.0f / (1.0f + __expf(-z));
}

// =====================================================================
// Kernel A: input projections for BOTH directions in one GEMM.
//   [B*T, 3072] = x[B*T,256] @ [Wx_f | Wx_b], scattered into g_gx with
//   time reversal for the backward direction.
// =====================================================================
__global__ void __launch_bounds__(256) k_inproj(
    const float* __restrict__ x,
    const float* __restrict__ Wxf,
    const float* __restrict__ Wxb)
{
    __shared__ __align__(16) float As[16 * 64];   // [k][m]
    __shared__ __align__(16) float Bs[16 * 64];   // [k][n]

    const int tid = threadIdx.x;
    const int m0  = blockIdx.x * 64;
    const int n0g = blockIdx.y * 64;
    const int dir = (n0g >= G3) ? 1 : 0;
    const float* __restrict__ W = dir ? Wxb : Wxf;
    const int n0 = n0g - dir * G3;

    const int bg = tid >> 4;
    const int ng = tid & 15;
    const int ar = tid >> 2, aq = tid & 3;
    const int bk = tid >> 4, bc = tid & 15;

    float acc[4][4];
#pragma unroll
    for (int i = 0; i < 4; i++)
#pragma unroll
        for (int j = 0; j < 4; j++) acc[i][j] = 0.0f;

    for (int k0 = 0; k0 < D_; k0 += 16) {
        float4 av = *reinterpret_cast<const float4*>(x + (size_t)(m0 + ar) * D_ + k0 + aq * 4);
        float4 bv = *reinterpret_cast<const float4*>(W + (size_t)(k0 + bk) * G3 + n0 + bc * 4);
        __syncthreads();
        As[(aq * 4 + 0) * 64 + ar] = av.x;
        As[(aq * 4 + 1) * 64 + ar] = av.y;
        As[(aq * 4 + 2) * 64 + ar] = av.z;
        As[(aq * 4 + 3) * 64 + ar] = av.w;
        *reinterpret_cast<float4*>(&Bs[bk * 64 + bc * 4]) = bv;
        __syncthreads();
#pragma unroll
        for (int kk = 0; kk < 16; kk++) {
            float4 a4 = *reinterpret_cast<const float4*>(&As[kk * 64 + bg * 4]);
            float4 b4 = *reinterpret_cast<const float4*>(&Bs[kk * 64 + ng * 4]);
            float a[4] = {a4.x, a4.y, a4.z, a4.w};
            float b[4] = {b4.x, b4.y, b4.z, b4.w};
#pragma unroll
            for (int i = 0; i < 4; i++)
#pragma unroll
                for (int j = 0; j < 4; j++) acc[i][j] += a[i] * b[j];
        }
    }

#pragma unroll
    for (int i = 0; i < 4; i++) {
        int m = m0 + bg * 4 + i;
        int b = m >> 9;
        int s = m & 511;
        int t = dir ? (T_ - 1 - s) : s;
        float* dst = g_gx + (((size_t)dir * T_ + t) * B_ + b) * G3 + n0 + ng * 4;
        *reinterpret_cast<float4*>(dst) =
            make_float4(acc[i][0], acc[i][1], acc[i][2], acc[i][3]);
    }
}

// =====================================================================
// Kernel B: persistent bidirectional GRU scan, 512 threads/block.
// blocks [0,64) = forward, [64,128) = backward. Per step:
//   Phase A: z = h @ Wh[:, :1024]; u, r gates; store u and r*h.
//   Phase B: c = (r*h) @ Wh[:, 1024:]; h' = h + u*(tanh(.) - h); out.
// Staging loads (L2-coherent ldcg) are double-buffered in registers so
// L2 latency hides under the previous chunk's FFMAs.
// =====================================================================
__global__ void __launch_bounds__(NTHR, 1) k_scan(
    const float* __restrict__ Whf, const float* __restrict__ Whb,
    const float* __restrict__ bf,  const float* __restrict__ bb,
    float* __restrict__ out)
{
    __shared__ __align__(16) float s_u[8192];   // 32KB: staging OR K-split partials

    const int tid = threadIdx.x;
    const int blk = blockIdx.x;
    const int dir = blk >> 6;
    const int sub = blk & 63;

    const float* __restrict__ Wh   = dir ? Whb : Whf;
    const float* __restrict__ bias = dir ? bb : bf;
    float* hbuf  = g_h  + dir * (B_ * U_);
    float* ubuf  = g_u  + dir * (B_ * U_);
    float* rhbuf = g_rh + dir * (B_ * U_);
    const float* gxbase = g_gx + (size_t)dir * T_ * B_ * G3;

    const int cbaseA = sub * 16;   // cols within [0,1024)
    const int cbaseB = sub * 8;    // cols within [0,512)

    // zero h for this launch (65536 floats, exactly 1 per thread)
    __stcg(&g_h[blk * NTHR + tid], 0.0f);
    dir_barrier(dir);

    // ---- Phase A mapping: 8 K-groups x 64 threads, 4x4 micro over 64b x 16c
    const int kgA = tid >> 6;                 // 0..7, K range 64 each
    const int t2  = tid & 63;
    const int b0A = (t2 >> 2) << 2;
    const int c0A = (t2 & 3) << 2;
    const int qA  = t2 & 3;                   // staging k-quad
    const int blA = t2 >> 2;                  // staging b base (j*16 + blA)
    // reduction outputs (2 per thread)
    const int oidA = tid << 1;
    const int bA0 = oidA >> 4,        cgA0 = cbaseA + (oidA & 15);
    const int bA1 = (oidA + 1) >> 4,  cgA1 = cbaseA + ((oidA + 1) & 15);
    const float biasA0 = __ldg(bias + cgA0);
    const float biasA1 = __ldg(bias + cgA1);

    // ---- Phase B mapping: 16 K-groups x 32 threads, 4x4 micro over 64b x 8c
    const int kgB = tid >> 5;                 // 0..15, K range 32 each
    const int t3  = tid & 31;
    const int b0B = (t3 >> 1) << 2;
    const int c0B = (t3 & 1) << 2;
    const int qB  = t3 & 1;                   // staging k-half
    const int blB = t3 >> 1;                  // staging b base (j*16 + blB)
    const int bB  = tid >> 3;                 // reduction output
    const int cgB = cbaseB + (tid & 7);
    const float biasB = __ldg(bias + 1024 + cgB);

    for (int t = 0; t < T_; t++) {
        const float* gxt = gxbase + (size_t)t * B_ * G3;

        // ================= Phase A =================
        {
            // prefetch this step's gx for our outputs (DRAM latency hides under GEMM)
            float gxa0 = __ldg(gxt + (size_t)bA0 * G3 + cgA0);
            float gxa1 = __ldg(gxt + (size_t)bA1 * G3 + cgA1);

            const int kb = kgA << 6;
            float4 pf[4];
#pragma unroll
            for (int j = 0; j < 4; j++)
                pf[j] = __ldcg(reinterpret_cast<const float4*>(
                    hbuf + (j * 16 + blA) * U_ + kb + qA * 4));

            float acc[4][4];
#pragma unroll
            for (int i = 0; i < 4; i++)
#pragma unroll
                for (int j = 0; j < 4; j++) acc[i][j] = 0.0f;

            for (int ch = 0; ch < 4; ch++) {
                const int k0 = kb + (ch << 4);
                __syncthreads();
#pragma unroll
                for (int j = 0; j < 4; j++) {
                    int base = (kgA << 10) + (qA << 2) * 64 + j * 16 + blA;
                    s_u[base]       = pf[j].x;
                    s_u[base + 64]  = pf[j].y;
                    s_u[base + 128] = pf[j].z;
                    s_u[base + 192] = pf[j].w;
                }
                __syncthreads();
                if (ch < 3) {
#pragma unroll
                    for (int j = 0; j < 4; j++)
                        pf[j] = __ldcg(reinterpret_cast<const float4*>(
                            hbuf + (j * 16 + blA) * U_ + k0 + 16 + qA * 4));
                }
#pragma unroll
                for (int kk = 0; kk < 16; kk++) {
                    float4 h4 = *reinterpret_cast<const float4*>(
                        &s_u[(kgA << 10) + kk * 64 + b0A]);
                    float4 w4 = *reinterpret_cast<const float4*>(
                        Wh + (size_t)(k0 + kk) * G3 + cbaseA + c0A);
                    float a[4] = {h4.x, h4.y, h4.z, h4.w};
                    float w[4] = {w4.x, w4.y, w4.z, w4.w};
#pragma unroll
                    for (int i = 0; i < 4; i++)
#pragma unroll
                        for (int j = 0; j < 4; j++) acc[i][j] += a[i] * w[j];
                }
            }
            __syncthreads();
#pragma unroll
            for (int i = 0; i < 4; i++)
#pragma unroll
                for (int j = 0; j < 4; j++)
                    s_u[(kgA << 10) + (b0A + i) * 16 + c0A + j] = acc[i][j];
            __syncthreads();

            // 2 outputs per thread
            {
                float z0 = 0.0f, z1 = 0.0f;
#pragma unroll
                for (int kg = 0; kg < 8; kg++) {
                    z0 += s_u[(kg << 10) + oidA];
                    z1 += s_u[(kg << 10) + oidA + 1];
                }
                float sg0 = sigmoidf_(z0 + gxa0 + biasA0);
                float sg1 = sigmoidf_(z1 + gxa1 + biasA1);
                if (cgA0 < U_) {
                    __stcg(ubuf + bA0 * U_ + cgA0, sg0);
                } else {
                    float hold = __ldcg(hbuf + bA0 * U_ + cgA0 - U_);
                    __stcg(rhbuf + bA0 * U_ + cgA0 - U_, sg0 * hold);
                }
                if (cgA1 < U_) {
                    __stcg(ubuf + bA1 * U_ + cgA1, sg1);
                } else {
                    float hold = __ldcg(hbuf + bA1 * U_ + cgA1 - U_);
                    __stcg(rhbuf + bA1 * U_ + cgA1 - U_, sg1 * hold);
                }
            }
        }
        dir_barrier(dir);

        // ================= Phase B =================
        {
            float gxb = __ldg(gxt + (size_t)bB * G3 + 1024 + cgB);

            const int kb = kgB << 5;
            float4 pf[4];
#pragma unroll
            for (int j = 0; j < 4; j++)
                pf[j] = __ldcg(reinterpret_cast<const float4*>(
                    rhbuf + (j * 16 + blB) * U_ + kb + qB * 4));

            float acc[4][4];
#pragma unroll
            for (int i = 0; i < 4; i++)
#pragma unroll
                for (int j = 0; j < 4; j++) acc[i][j] = 0.0f;

            for (int ch = 0; ch < 4; ch++) {
                const int k0 = kb + (ch << 3);
                __syncthreads();
#pragma unroll
                for (int j = 0; j < 4; j++) {
                    int base = (kgB << 9) + (qB << 2) * 64 + j * 16 + blB;
                    s_u[base]       = pf[j].x;
                    s_u[base + 64]  = pf[j].y;
                    s_u[base + 128] = pf[j].z;
                    s_u[base + 192] = pf[j].w;
                }
                __syncthreads();
                if (ch < 3) {
#pragma unroll
                    for (int j = 0; j < 4; j++)
                        pf[j] = __ldcg(reinterpret_cast<const float4*>(
                            rhbuf + (j * 16 + blB) * U_ + k0 + 8 + qB * 4));
                }
#pragma unroll
                for (int kk = 0; kk < 8; kk++) {
                    float4 h4 = *reinterpret_cast<const float4*>(
                        &s_u[(kgB << 9) + kk * 64 + b0B]);
                    float4 w4 = *reinterpret_cast<const float4*>(
                        Wh + (size_t)(k0 + kk) * G3 + 1024 + cbaseB + c0B);
                    float a[4] = {h4.x, h4.y, h4.z, h4.w};
                    float w[4] = {w4.x, w4.y, w4.z, w4.w};
#pragma unroll
                    for (int i = 0; i < 4; i++)
#pragma unroll
                        for (int j = 0; j < 4; j++) acc[i][j] += a[i] * w[j];
                }
            }
            __syncthreads();
#pragma unroll
            for (int i = 0; i < 4; i++)
#pragma unroll
                for (int j = 0; j < 4; j++)
                    s_u[(kgB << 9) + (b0B + i) * 8 + c0B + j] = acc[i][j];
            __syncthreads();

            // 1 output per thread
            {
                float z = 0.0f;
#pragma unroll
                for (int kg = 0; kg < 16; kg++) z += s_u[(kg << 9) + tid];
                float hh   = tanhf(z + gxb + biasB);
                float uu   = __ldcg(ubuf + bB * U_ + cgB);
                float hold = __ldcg(hbuf + bB * U_ + cgB);
                float hnew = hold + uu * (hh - hold);
                __stcg(hbuf + bB * U_ + cgB, hnew);
                out[((size_t)bB * T_ + t) * 1024 + dir * U_ + cgB] = hnew;
            }
        }
        dir_barrier(dir);
    }
}

// =====================================================================
extern "C" void kernel_launch(void* const* d_in, const int* in_sizes, int n_in,
                              void* d_out, int out_size)
{
    const float* x   = (const float*)d_in[0];
    const float* Wxf = (const float*)d_in[1];
    const float* Whf = (const float*)d_in[2];
    const float* bf  = (const float*)d_in[3];
    const float* Wxb = (const float*)d_in[4];
    const float* Whb = (const float*)d_in[5];
    const float* bb  = (const float*)d_in[6];
    float* out = (float*)d_out;

    dim3 gA(512, 48);
    k_inproj<<<gA, 256>>>(x, Wxf, Wxb);
    k_scan<<<NBLK, NTHR>>>(Whf, Whb, bf, bb, out);
}